// round 14
// baseline (speedup 1.0000x reference)
#include <cuda_runtime.h>
#include <cstdint>

#define N_NODES 100000
#define D 128
#define N_EDGES 1600000
#define TILE 32
#define NTILES (N_NODES / TILE)      // 3125 exact
#define NB_SCAN ((N_NODES + 255) / 256)

__device__ int g_cnt[N_NODES];
__device__ int g_rs[N_NODES + 1];
__device__ int g_esrc[N_EDGES];
__device__ int g_bsum[512];
__device__ int g_is64;

// ---------------- packed f32x2 helpers (validated) ----------------
__device__ __forceinline__ unsigned long long fma2(unsigned long long a,
                                                   unsigned long long b,
                                                   unsigned long long c) {
    unsigned long long d;
    asm("fma.rn.f32x2 %0, %1, %2, %3;" : "=l"(d) : "l"(a), "l"(b), "l"(c));
    return d;
}
__device__ __forceinline__ unsigned long long dup2(float a) {
    unsigned long long d;
    asm("mov.b64 %0, {%1, %1};" : "=l"(d) : "f"(a));
    return d;
}
__device__ __forceinline__ float2 unpack2(unsigned long long v) {
    float2 r;
    asm("mov.b64 {%0, %1}, %2;" : "=f"(r.x), "=f"(r.y) : "l"(v));
    return r;
}

// ---------------- kernel 1: zero counts + dtype sniff ----------------
__global__ void zero_sniff_kernel(const void* __restrict__ src) {
    int i = blockIdx.x * blockDim.x + threadIdx.x;
    if (i < N_NODES) g_cnt[i] = 0;
    if (i == 0) {
        const long long* p = (const long long*)src;
        int ok = 1;
        #pragma unroll 1
        for (int q = 0; q < 64; q++) {
            long long v = p[q];
            if (v < 0 || v >= N_NODES) { ok = 0; break; }
        }
        g_is64 = ok;
    }
}

// ---------------- kernel 2: count in-degrees (dst only) ----------------
__global__ void count_kernel(const void* __restrict__ dst_raw) {
    const int is64 = g_is64;
    int idx = blockIdx.x * blockDim.x + threadIdx.x;
    int stride = gridDim.x * blockDim.x;
    for (int e = idx; e < N_EDGES; e += stride) {
        int d = is64 ? (int)((const long long*)dst_raw)[e]
                     : ((const int*)dst_raw)[e];
        if ((unsigned)d < N_NODES) atomicAdd(&g_cnt[d], 1);
    }
}

// ---------------- scan (validated R4-R6) ----------------
__global__ void scan1_kernel() {
    __shared__ int sm[256];
    int gi = blockIdx.x * 256 + threadIdx.x;
    sm[threadIdx.x] = (gi < N_NODES) ? g_cnt[gi] : 0;
    __syncthreads();
    for (int off = 128; off > 0; off >>= 1) {
        if (threadIdx.x < off) sm[threadIdx.x] += sm[threadIdx.x + off];
        __syncthreads();
    }
    if (threadIdx.x == 0) g_bsum[blockIdx.x] = sm[0];
}
__global__ void scan2_kernel() {
    __shared__ int sm[512];
    int t = threadIdx.x;
    sm[t] = (t < NB_SCAN) ? g_bsum[t] : 0;
    __syncthreads();
    for (int off = 1; off < 512; off <<= 1) {
        int v = (t >= off) ? sm[t - off] : 0;
        __syncthreads();
        sm[t] += v;
        __syncthreads();
    }
    int ex = (t == 0) ? 0 : sm[t - 1];
    if (t < NB_SCAN) g_bsum[t] = ex;
    if (t == NB_SCAN) g_rs[N_NODES] = sm[NB_SCAN - 1];
}
__global__ void scan3_kernel() {
    __shared__ int sm[256];
    int b = blockIdx.x, t = threadIdx.x;
    int gi = b * 256 + t;
    int c = (gi < N_NODES) ? g_cnt[gi] : 0;
    sm[t] = c;
    __syncthreads();
    for (int off = 1; off < 256; off <<= 1) {
        int v = (t >= off) ? sm[t - off] : 0;
        __syncthreads();
        sm[t] += v;
        __syncthreads();
    }
    int ex = sm[t] - c;
    if (gi < N_NODES) {
        g_rs[gi] = g_bsum[b] + ex;
        g_cnt[gi] = 0;
    }
}

// ---------------- kernel 3: fill CSR (validated R4-R6) ----------------
__global__ void fill_kernel(const void* __restrict__ src_raw,
                            const void* __restrict__ dst_raw) {
    const int is64 = g_is64;
    int idx = blockIdx.x * blockDim.x + threadIdx.x;
    int stride = gridDim.x * blockDim.x;
    for (int e = idx; e < N_EDGES; e += stride) {
        int s, d;
        if (is64) {
            s = (int)((const long long*)src_raw)[e];
            d = (int)((const long long*)dst_raw)[e];
        } else {
            s = ((const int*)src_raw)[e];
            d = ((const int*)dst_raw)[e];
        }
        if ((unsigned)s < N_NODES && (unsigned)d < N_NODES) {
            int pos = atomicAdd(&g_cnt[d], 1);
            g_esrc[g_rs[d] + pos] = s;
        }
    }
}

// ---------------- fused kernel: 8 compute + 8 gather warps, two-pass GEMM ----------------
// 512 threads. Warps 0-7 compute: 2/SMSP interleave so one warp's FFMA stream
// hides the other's LDS latency. Thread tile 4 rows x 4 cols, TWO-PASS
// (self x Ws, then neigh x Wn) for low register pressure (R6-proven shape).
// Warps 8-15 gather: 4 rows each, compact CSR, MLP=8 (R6-proven).
// SMEM floats: sWs[16384] sWn[16384] | 2 bufs x (Xs[4096] Xn[4096]) = 192 KB.
__global__ __launch_bounds__(512, 1)
void fused_kernel(const float* __restrict__ h,
                  const float* __restrict__ Ws,
                  const float* __restrict__ Wn,
                  float* __restrict__ out) {
    extern __shared__ float sm[];
    float* sWs = sm;
    float* sWn = sm + 16384;
    float* sX  = sm + 32768;  // [2 bufs][self 4096 | neigh 4096]

    int tid = threadIdx.x, wid = tid >> 5, lane = tid & 31;
    const bool is_gather = (wid >= 8);

    auto fill_tile = [&](int tile, int buf) {
        float* bXs = sX + buf * 8192;
        float* bXn = bXs + 4096;
        int gwid = wid - 8;  // 0..7
        #pragma unroll 1
        for (int rr = 0; rr < 4; rr++) {
            int r = gwid * 4 + rr;
            int row = tile * TILE + r;
            float4 self = reinterpret_cast<const float4*>(h + (size_t)row * D)[lane];
            int beg = g_rs[row], end = g_rs[row + 1];
            float inv = 1.0f / fmaxf((float)(end - beg), 1.0f);
            float4 acc = make_float4(0.f, 0.f, 0.f, 0.f);
            int e = beg;
            #pragma unroll 1
            for (; e + 8 <= end; e += 8) {
                int si[8];
                #pragma unroll
                for (int q = 0; q < 8; q++) si[q] = g_esrc[e + q];
                float4 v[8];
                #pragma unroll
                for (int q = 0; q < 8; q++)
                    v[q] = reinterpret_cast<const float4*>(h + (size_t)si[q] * D)[lane];
                #pragma unroll
                for (int q = 0; q < 8; q++) {
                    acc.x += v[q].x; acc.y += v[q].y;
                    acc.z += v[q].z; acc.w += v[q].w;
                }
            }
            #pragma unroll 1
            for (; e < end; e++) {
                float4 v0 = reinterpret_cast<const float4*>(h + (size_t)g_esrc[e] * D)[lane];
                acc.x += v0.x; acc.y += v0.y; acc.z += v0.z; acc.w += v0.w;
            }
            reinterpret_cast<float4*>(bXs + r * D)[lane] = self;
            reinterpret_cast<float4*>(bXn + r * D)[lane] =
                make_float4(acc.x * inv, acc.y * inv, acc.z * inv, acc.w * inv);
        }
    };

    // prologue: compute warps load W; gather warps fill buf0
    int t0 = blockIdx.x;
    if (is_gather) {
        if (t0 < NTILES) fill_tile(t0, 0);
    } else {
        for (int i = tid; i < 4096; i += 256) {
            reinterpret_cast<float4*>(sWs)[i] = reinterpret_cast<const float4*>(Ws)[i];
            reinterpret_cast<float4*>(sWn)[i] = reinterpret_cast<const float4*>(Wn)[i];
        }
    }
    __syncthreads();

    int p = 0;
    const int c0 = lane * 4;   // compute cols
    const int r0 = wid * 4;    // compute rows (wid 0..7 -> rows 0..31)

    for (int t = t0; t < NTILES; t += gridDim.x) {
        if (is_gather) {
            int tn = t + gridDim.x;
            if (tn < NTILES) fill_tile(tn, p ^ 1);
        } else {
            float* bXs = sX + p * 8192;
            float* bXn = bXs + 4096;

            unsigned long long accu[4][2];
            #pragma unroll
            for (int i = 0; i < 4; i++) { accu[i][0] = 0ull; accu[i][1] = 0ull; }

            // pass 1: self x Ws
            #pragma unroll 1
            for (int kk = 0; kk < D; kk += 4) {
                float4 a[4];
                #pragma unroll
                for (int i = 0; i < 4; i++)
                    a[i] = *reinterpret_cast<const float4*>(bXs + (r0 + i) * D + kk);
                #pragma unroll
                for (int dk = 0; dk < 4; dk++) {
                    ulonglong2 w2 = *reinterpret_cast<const ulonglong2*>(sWs + (kk + dk) * D + c0);
                    #pragma unroll
                    for (int i = 0; i < 4; i++) {
                        unsigned long long a2 = dup2(reinterpret_cast<const float*>(&a[i])[dk]);
                        accu[i][0] = fma2(a2, w2.x, accu[i][0]);
                        accu[i][1] = fma2(a2, w2.y, accu[i][1]);
                    }
                }
            }
            // pass 2: neigh x Wn
            #pragma unroll 1
            for (int kk = 0; kk < D; kk += 4) {
                float4 a[4];
                #pragma unroll
                for (int i = 0; i < 4; i++)
                    a[i] = *reinterpret_cast<const float4*>(bXn + (r0 + i) * D + kk);
                #pragma unroll
                for (int dk = 0; dk < 4; dk++) {
                    ulonglong2 w2 = *reinterpret_cast<const ulonglong2*>(sWn + (kk + dk) * D + c0);
                    #pragma unroll
                    for (int i = 0; i < 4; i++) {
                        unsigned long long a2 = dup2(reinterpret_cast<const float*>(&a[i])[dk]);
                        accu[i][0] = fma2(a2, w2.x, accu[i][0]);
                        accu[i][1] = fma2(a2, w2.y, accu[i][1]);
                    }
                }
            }

            #pragma unroll
            for (int i = 0; i < 4; i++) {
                int row = t * TILE + r0 + i;
                float2 lo = unpack2(accu[i][0]);
                float2 hi = unpack2(accu[i][1]);
                *reinterpret_cast<float4*>(out + (size_t)row * D + c0) =
                    make_float4(lo.x, lo.y, hi.x, hi.y);
            }
        }
        __syncthreads();
        p ^= 1;
    }
}

// ---------------- launch ----------------
extern "C" void kernel_launch(void* const* d_in, const int* in_sizes, int n_in,
                              void* d_out, int out_size) {
    const float* h      = (const float*)d_in[0];
    const void*  src    = d_in[1];
    const void*  dst    = d_in[2];
    const float* Wself  = (const float*)d_in[3];
    const float* Wneigh = (const float*)d_in[4];
    float*       out    = (float*)d_out;

    static bool attr_set = false;
    if (!attr_set) {
        cudaFuncSetAttribute(fused_kernel,
                             cudaFuncAttributeMaxDynamicSharedMemorySize,
                             196608);
        attr_set = true;
    }

    zero_sniff_kernel<<<NB_SCAN, 256>>>(src);
    count_kernel<<<2048, 256>>>(dst);
    scan1_kernel<<<NB_SCAN, 256>>>();
    scan2_kernel<<<1, 512>>>();
    scan3_kernel<<<NB_SCAN, 256>>>();
    fill_kernel<<<2048, 256>>>(src, dst);
    fused_kernel<<<148, 512, 196608>>>(h, Wself, Wneigh, out);
}

// round 15
// speedup vs baseline: 1.0972x; 1.0972x over previous
#include <cuda_runtime.h>
#include <cstdint>

#define N_NODES 100000
#define D 128
#define N_EDGES 1600000
#define TILE 32
#define NTILES (N_NODES / TILE)      // 3125 exact
#define NB_B 391                      // build blocks: 391*256 = 100096 >= N_NODES+1

__device__ int g_cnt[N_NODES];
__device__ int g_rs[N_NODES + 1];
__device__ int g_esrc[N_EDGES];
__device__ int g_bsum[NB_B];
__device__ int g_is64;
__device__ unsigned g_bar1, g_bar2;

// ---------------- packed f32x2 helpers (validated) ----------------
__device__ __forceinline__ unsigned long long fma2(unsigned long long a,
                                                   unsigned long long b,
                                                   unsigned long long c) {
    unsigned long long d;
    asm("fma.rn.f32x2 %0, %1, %2, %3;" : "=l"(d) : "l"(a), "l"(b), "l"(c));
    return d;
}
__device__ __forceinline__ unsigned long long dup2(float a) {
    unsigned long long d;
    asm("mov.b64 %0, {%1, %1};" : "=l"(d) : "f"(a));
    return d;
}
__device__ __forceinline__ float2 unpack2(unsigned long long v) {
    float2 r;
    asm("mov.b64 {%0, %1}, %2;" : "=f"(r.x), "=f"(r.y) : "l"(v));
    return r;
}

// ---------------- kernel 1: zero counts + dtype sniff + barrier reset ----------------
__global__ void zero_sniff_kernel(const void* __restrict__ src) {
    int i = blockIdx.x * blockDim.x + threadIdx.x;
    if (i < N_NODES) g_cnt[i] = 0;
    if (i == 0) {
        g_bar1 = 0u; g_bar2 = 0u;
        const long long* p = (const long long*)src;
        int ok = 1;
        #pragma unroll 1
        for (int q = 0; q < 64; q++) {
            long long v = p[q];
            if (v < 0 || v >= N_NODES) { ok = 0; break; }
        }
        g_is64 = ok;
    }
}

// ---------------- kernel 2: count in-degrees (dst only) ----------------
__global__ void count_kernel(const void* __restrict__ dst_raw) {
    const int is64 = g_is64;
    int idx = blockIdx.x * blockDim.x + threadIdx.x;
    int stride = gridDim.x * blockDim.x;
    for (int e = idx; e < N_EDGES; e += stride) {
        int d = is64 ? (int)((const long long*)dst_raw)[e]
                     : ((const int*)dst_raw)[e];
        if ((unsigned)d < N_NODES) atomicAdd(&g_cnt[d], 1);
    }
}

// ---------------- grid barrier (all blocks resident) ----------------
__device__ __forceinline__ void grid_barrier(unsigned* bar, int nblocks) {
    __syncthreads();
    if (threadIdx.x == 0) {
        __threadfence();
        atomicAdd(bar, 1u);
        while (atomicAdd(bar, 0u) < (unsigned)nblocks) __nanosleep(64);
    }
    __syncthreads();
}

// ---------------- kernel 3: scan + fill in one resident kernel ----------------
// 391 blocks x 256 threads (no smem constraint -> all resident, barrier safe).
__global__ void build_kernel(const void* __restrict__ src_raw,
                             const void* __restrict__ dst_raw) {
    __shared__ int sm[256];
    __shared__ int s_pre;
    int b = blockIdx.x, t = threadIdx.x;
    int gi = b * 256 + t;

    // block-inclusive scan of counts
    int c = (gi < N_NODES) ? g_cnt[gi] : 0;
    sm[t] = c;
    __syncthreads();
    for (int off = 1; off < 256; off <<= 1) {
        int v = (t >= off) ? sm[t - off] : 0;
        __syncthreads();
        sm[t] += v;
        __syncthreads();
    }
    int incl = sm[t];
    if (t == 255) g_bsum[b] = incl;   // block total
    __syncthreads();                  // protect sm reuse below

    grid_barrier(&g_bar1, NB_B);      // all block totals visible

    // each block computes its exclusive prefix over g_bsum[0..b)
    int part = 0;
    for (int i = t; i < b; i += 256) part += g_bsum[i];
    sm[t] = part;
    __syncthreads();
    for (int off = 128; off > 0; off >>= 1) {
        if (t < off) sm[t] += sm[t + off];
        __syncthreads();
    }
    if (t == 0) s_pre = sm[0];
    __syncthreads();
    int pre = s_pre;

    if (gi <= N_NODES) {
        g_rs[gi] = pre + incl - c;    // exclusive row start
        if (gi < N_NODES) g_cnt[gi] = 0;  // reset -> fill cursor
    }

    grid_barrier(&g_bar2, NB_B);      // row starts + cursors visible

    // CSR fill (grid-stride over edges)
    const int is64 = g_is64;
    const int stride = NB_B * 256;
    #pragma unroll 1
    for (int e = b * 256 + t; e < N_EDGES; e += stride) {
        int s, d;
        if (is64) {
            s = (int)((const long long*)src_raw)[e];
            d = (int)((const long long*)dst_raw)[e];
        } else {
            s = ((const int*)src_raw)[e];
            d = ((const int*)dst_raw)[e];
        }
        if ((unsigned)s < N_NODES && (unsigned)d < N_NODES) {
            int pos = atomicAdd(&g_cnt[d], 1);
            g_esrc[g_rs[d] + pos] = s;
        }
    }
}

// ---------------- kernel 4: fused (R6 champion, byte-for-byte) ----------------
// 384 threads: warps 0-3 compute (8 rows x 4 cols / thread, two-pass),
// warps 4-11 gather (4 rows each, compact CSR, MLP=8).
// SMEM floats: sWs[16384] sWn[16384] | 2 bufs x (Xs[4096] Xn[4096]) = 192 KB.
__global__ __launch_bounds__(384, 1)
void fused_kernel(const float* __restrict__ h,
                  const float* __restrict__ Ws,
                  const float* __restrict__ Wn,
                  float* __restrict__ out) {
    extern __shared__ float sm[];
    float* sWs = sm;
    float* sWn = sm + 16384;
    float* sX  = sm + 32768;  // [2 bufs][self 4096 | neigh 4096]

    int tid = threadIdx.x, wid = tid >> 5, lane = tid & 31;
    const bool is_gather = (wid >= 4);

    auto fill_tile = [&](int tile, int buf) {
        float* bXs = sX + buf * 8192;
        float* bXn = bXs + 4096;
        int gwid = wid - 4;  // 0..7
        #pragma unroll 1
        for (int rr = 0; rr < 4; rr++) {
            int r = gwid * 4 + rr;
            int row = tile * TILE + r;
            float4 self = reinterpret_cast<const float4*>(h + (size_t)row * D)[lane];
            int beg = g_rs[row], end = g_rs[row + 1];
            float inv = 1.0f / fmaxf((float)(end - beg), 1.0f);
            float4 acc = make_float4(0.f, 0.f, 0.f, 0.f);
            int e = beg;
            #pragma unroll 1
            for (; e + 8 <= end; e += 8) {
                int si[8];
                #pragma unroll
                for (int q = 0; q < 8; q++) si[q] = g_esrc[e + q];
                float4 v[8];
                #pragma unroll
                for (int q = 0; q < 8; q++)
                    v[q] = reinterpret_cast<const float4*>(h + (size_t)si[q] * D)[lane];
                #pragma unroll
                for (int q = 0; q < 8; q++) {
                    acc.x += v[q].x; acc.y += v[q].y;
                    acc.z += v[q].z; acc.w += v[q].w;
                }
            }
            #pragma unroll 1
            for (; e < end; e++) {
                float4 v0 = reinterpret_cast<const float4*>(h + (size_t)g_esrc[e] * D)[lane];
                acc.x += v0.x; acc.y += v0.y; acc.z += v0.z; acc.w += v0.w;
            }
            reinterpret_cast<float4*>(bXs + r * D)[lane] = self;
            reinterpret_cast<float4*>(bXn + r * D)[lane] =
                make_float4(acc.x * inv, acc.y * inv, acc.z * inv, acc.w * inv);
        }
    };

    // prologue: compute warps load W; gather warps fill buf0
    int t0 = blockIdx.x;
    if (is_gather) {
        if (t0 < NTILES) fill_tile(t0, 0);
    } else {
        for (int i = tid; i < 4096; i += 128) {
            reinterpret_cast<float4*>(sWs)[i] = reinterpret_cast<const float4*>(Ws)[i];
            reinterpret_cast<float4*>(sWn)[i] = reinterpret_cast<const float4*>(Wn)[i];
        }
    }
    __syncthreads();

    int p = 0;
    const int c0 = lane * 4;   // compute cols
    const int r0 = wid * 8;    // compute rows (wid 0..3 -> rows 0..31)

    for (int t = t0; t < NTILES; t += gridDim.x) {
        if (is_gather) {
            int tn = t + gridDim.x;
            if (tn < NTILES) fill_tile(tn, p ^ 1);
        } else {
            float* bXs = sX + p * 8192;
            float* bXn = bXs + 4096;

            unsigned long long accu[8][2];
            #pragma unroll
            for (int i = 0; i < 8; i++) { accu[i][0] = 0ull; accu[i][1] = 0ull; }

            // pass 1: self x Ws
            #pragma unroll 1
            for (int kk = 0; kk < D; kk += 4) {
                float4 a[8];
                #pragma unroll
                for (int i = 0; i < 8; i++)
                    a[i] = *reinterpret_cast<const float4*>(bXs + (r0 + i) * D + kk);
                #pragma unroll
                for (int dk = 0; dk < 4; dk++) {
                    ulonglong2 w2 = *reinterpret_cast<const ulonglong2*>(sWs + (kk + dk) * D + c0);
                    #pragma unroll
                    for (int i = 0; i < 8; i++) {
                        unsigned long long a2 = dup2(reinterpret_cast<const float*>(&a[i])[dk]);
                        accu[i][0] = fma2(a2, w2.x, accu[i][0]);
                        accu[i][1] = fma2(a2, w2.y, accu[i][1]);
                    }
                }
            }
            // pass 2: neigh x Wn
            #pragma unroll 1
            for (int kk = 0; kk < D; kk += 4) {
                float4 a[8];
                #pragma unroll
                for (int i = 0; i < 8; i++)
                    a[i] = *reinterpret_cast<const float4*>(bXn + (r0 + i) * D + kk);
                #pragma unroll
                for (int dk = 0; dk < 4; dk++) {
                    ulonglong2 w2 = *reinterpret_cast<const ulonglong2*>(sWn + (kk + dk) * D + c0);
                    #pragma unroll
                    for (int i = 0; i < 8; i++) {
                        unsigned long long a2 = dup2(reinterpret_cast<const float*>(&a[i])[dk]);
                        accu[i][0] = fma2(a2, w2.x, accu[i][0]);
                        accu[i][1] = fma2(a2, w2.y, accu[i][1]);
                    }
                }
            }

            #pragma unroll
            for (int i = 0; i < 8; i++) {
                int row = t * TILE + r0 + i;
                float2 lo = unpack2(accu[i][0]);
                float2 hi = unpack2(accu[i][1]);
                *reinterpret_cast<float4*>(out + (size_t)row * D + c0) =
                    make_float4(lo.x, lo.y, hi.x, hi.y);
            }
        }
        __syncthreads();
        p ^= 1;
    }
}

// ---------------- launch ----------------
extern "C" void kernel_launch(void* const* d_in, const int* in_sizes, int n_in,
                              void* d_out, int out_size) {
    const float* h      = (const float*)d_in[0];
    const void*  src    = d_in[1];
    const void*  dst    = d_in[2];
    const float* Wself  = (const float*)d_in[3];
    const float* Wneigh = (const float*)d_in[4];
    float*       out    = (float*)d_out;

    static bool attr_set = false;
    if (!attr_set) {
        cudaFuncSetAttribute(fused_kernel,
                             cudaFuncAttributeMaxDynamicSharedMemorySize,
                             196608);
        attr_set = true;
    }

    zero_sniff_kernel<<<NB_B, 256>>>(src);
    count_kernel<<<2048, 256>>>(dst);
    build_kernel<<<NB_B, 256>>>(src, dst);
    fused_kernel<<<152, 384, 196608>>>(h, Wself, Wneigh, out);
}

// round 16
// speedup vs baseline: 1.1000x; 1.0026x over previous
#include <cuda_runtime.h>
#include <cstdint>

#define N_NODES 100000
#define D 128
#define N_EDGES 1600000
#define TILE 32
#define NTILES (N_NODES / TILE)      // 3125 exact
#define NB_B 391                      // build blocks: 391*256 = 100096 >= N_NODES+1

__device__ int g_cnt[N_NODES];
__device__ int g_rs[N_NODES + 1];
__device__ int g_esrc[N_EDGES];
__device__ int g_bsum[NB_B];
__device__ int g_is64;
__device__ unsigned g_bar1, g_bar2;

// ---------------- packed f32x2 helpers (validated; FFMA2 confirmed by R14 profile) ----------------
__device__ __forceinline__ unsigned long long fma2(unsigned long long a,
                                                   unsigned long long b,
                                                   unsigned long long c) {
    unsigned long long d;
    asm("fma.rn.f32x2 %0, %1, %2, %3;" : "=l"(d) : "l"(a), "l"(b), "l"(c));
    return d;
}
__device__ __forceinline__ unsigned long long dup2(float a) {
    unsigned long long d;
    asm("mov.b64 %0, {%1, %1};" : "=l"(d) : "f"(a));
    return d;
}
__device__ __forceinline__ float2 unpack2(unsigned long long v) {
    float2 r;
    asm("mov.b64 {%0, %1}, %2;" : "=f"(r.x), "=f"(r.y) : "l"(v));
    return r;
}

// ---------------- kernel 1: zero counts + dtype sniff + barrier reset ----------------
__global__ void zero_sniff_kernel(const void* __restrict__ src) {
    int i = blockIdx.x * blockDim.x + threadIdx.x;
    if (i < N_NODES) g_cnt[i] = 0;
    if (i == 0) {
        g_bar1 = 0u; g_bar2 = 0u;
        const long long* p = (const long long*)src;
        int ok = 1;
        #pragma unroll 1
        for (int q = 0; q < 64; q++) {
            long long v = p[q];
            if (v < 0 || v >= N_NODES) { ok = 0; break; }
        }
        g_is64 = ok;
    }
}

// ---------------- kernel 2: count in-degrees (dst only) ----------------
__global__ void count_kernel(const void* __restrict__ dst_raw) {
    const int is64 = g_is64;
    int idx = blockIdx.x * blockDim.x + threadIdx.x;
    int stride = gridDim.x * blockDim.x;
    for (int e = idx; e < N_EDGES; e += stride) {
        int d = is64 ? (int)((const long long*)dst_raw)[e]
                     : ((const int*)dst_raw)[e];
        if ((unsigned)d < N_NODES) atomicAdd(&g_cnt[d], 1);
    }
}

// ---------------- grid barrier (all blocks resident) ----------------
__device__ __forceinline__ void grid_barrier(unsigned* bar, int nblocks) {
    __syncthreads();
    if (threadIdx.x == 0) {
        __threadfence();
        atomicAdd(bar, 1u);
        while (atomicAdd(bar, 0u) < (unsigned)nblocks) __nanosleep(64);
    }
    __syncthreads();
}

// ---------------- kernel 3: scan + fill in one resident kernel (validated R14) ----------------
__global__ void build_kernel(const void* __restrict__ src_raw,
                             const void* __restrict__ dst_raw) {
    __shared__ int sm[256];
    __shared__ int s_pre;
    int b = blockIdx.x, t = threadIdx.x;
    int gi = b * 256 + t;

    int c = (gi < N_NODES) ? g_cnt[gi] : 0;
    sm[t] = c;
    __syncthreads();
    for (int off = 1; off < 256; off <<= 1) {
        int v = (t >= off) ? sm[t - off] : 0;
        __syncthreads();
        sm[t] += v;
        __syncthreads();
    }
    int incl = sm[t];
    if (t == 255) g_bsum[b] = incl;
    __syncthreads();

    grid_barrier(&g_bar1, NB_B);

    int part = 0;
    for (int i = t; i < b; i += 256) part += g_bsum[i];
    sm[t] = part;
    __syncthreads();
    for (int off = 128; off > 0; off >>= 1) {
        if (t < off) sm[t] += sm[t + off];
        __syncthreads();
    }
    if (t == 0) s_pre = sm[0];
    __syncthreads();
    int pre = s_pre;

    if (gi <= N_NODES) {
        g_rs[gi] = pre + incl - c;
        if (gi < N_NODES) g_cnt[gi] = 0;
    }

    grid_barrier(&g_bar2, NB_B);

    const int is64 = g_is64;
    const int stride = NB_B * 256;
    #pragma unroll 1
    for (int e = b * 256 + t; e < N_EDGES; e += stride) {
        int s, d;
        if (is64) {
            s = (int)((const long long*)src_raw)[e];
            d = (int)((const long long*)dst_raw)[e];
        } else {
            s = ((const int*)src_raw)[e];
            d = ((const int*)dst_raw)[e];
        }
        if ((unsigned)s < N_NODES && (unsigned)d < N_NODES) {
            int pos = atomicAdd(&g_cnt[d], 1);
            g_esrc[g_rs[d] + pos] = s;
        }
    }
}

// ---------------- kernel 4: fused (R6 structure + register-pipelined GEMM) ----------------
// 384 threads: warps 0-3 compute (8 rows x 4 cols, two-pass, double-buffered
// kk loop hides LDS latency under the fma2 stream), warps 4-11 gather.
// SMEM floats: sWs[16384] sWn[16384] | 2 bufs x (Xs[4096] Xn[4096]) = 192 KB.
__global__ __launch_bounds__(384, 1)
void fused_kernel(const float* __restrict__ h,
                  const float* __restrict__ Ws,
                  const float* __restrict__ Wn,
                  float* __restrict__ out) {
    extern __shared__ float sm[];
    float* sWs = sm;
    float* sWn = sm + 16384;
    float* sX  = sm + 32768;  // [2 bufs][self 4096 | neigh 4096]

    int tid = threadIdx.x, wid = tid >> 5, lane = tid & 31;
    const bool is_gather = (wid >= 4);

    auto fill_tile = [&](int tile, int buf) {
        float* bXs = sX + buf * 8192;
        float* bXn = bXs + 4096;
        int gwid = wid - 4;  // 0..7
        #pragma unroll 1
        for (int rr = 0; rr < 4; rr++) {
            int r = gwid * 4 + rr;
            int row = tile * TILE + r;
            float4 self = reinterpret_cast<const float4*>(h + (size_t)row * D)[lane];
            int beg = g_rs[row], end = g_rs[row + 1];
            float inv = 1.0f / fmaxf((float)(end - beg), 1.0f);
            float4 acc = make_float4(0.f, 0.f, 0.f, 0.f);
            int e = beg;
            #pragma unroll 1
            for (; e + 8 <= end; e += 8) {
                int si[8];
                #pragma unroll
                for (int q = 0; q < 8; q++) si[q] = g_esrc[e + q];
                float4 v[8];
                #pragma unroll
                for (int q = 0; q < 8; q++)
                    v[q] = reinterpret_cast<const float4*>(h + (size_t)si[q] * D)[lane];
                #pragma unroll
                for (int q = 0; q < 8; q++) {
                    acc.x += v[q].x; acc.y += v[q].y;
                    acc.z += v[q].z; acc.w += v[q].w;
                }
            }
            #pragma unroll 1
            for (; e < end; e++) {
                float4 v0 = reinterpret_cast<const float4*>(h + (size_t)g_esrc[e] * D)[lane];
                acc.x += v0.x; acc.y += v0.y; acc.z += v0.z; acc.w += v0.w;
            }
            reinterpret_cast<float4*>(bXs + r * D)[lane] = self;
            reinterpret_cast<float4*>(bXn + r * D)[lane] =
                make_float4(acc.x * inv, acc.y * inv, acc.z * inv, acc.w * inv);
        }
    };

    // prologue
    int t0 = blockIdx.x;
    if (is_gather) {
        if (t0 < NTILES) fill_tile(t0, 0);
    } else {
        for (int i = tid; i < 4096; i += 128) {
            reinterpret_cast<float4*>(sWs)[i] = reinterpret_cast<const float4*>(Ws)[i];
            reinterpret_cast<float4*>(sWn)[i] = reinterpret_cast<const float4*>(Wn)[i];
        }
    }
    __syncthreads();

    int p = 0;
    const int c0 = lane * 4;   // compute cols
    const int r0 = wid * 8;    // compute rows (wid 0..3 -> rows 0..31)

    for (int t = t0; t < NTILES; t += gridDim.x) {
        if (is_gather) {
            int tn = t + gridDim.x;
            if (tn < NTILES) fill_tile(tn, p ^ 1);
        } else {
            float* bXs = sX + p * 8192;
            float* bXn = bXs + 4096;

            unsigned long long accu[8][2];
            #pragma unroll
            for (int i = 0; i < 8; i++) { accu[i][0] = 0ull; accu[i][1] = 0ull; }

            // register-pipelined pass (macro: prefetch next chunk under fma2 stream)
            #define GEMM_PASS(bX, sW)                                                   \
            {                                                                           \
                float4 a0[8], a1[8];                                                    \
                ulonglong2 w0[4], w1[4];                                                \
                _Pragma("unroll")                                                       \
                for (int i = 0; i < 8; i++)                                             \
                    a0[i] = *reinterpret_cast<const float4*>((bX) + (r0 + i) * D);      \
                _Pragma("unroll")                                                       \
                for (int dk = 0; dk < 4; dk++)                                          \
                    w0[dk] = *reinterpret_cast<const ulonglong2*>((sW) + dk * D + c0);  \
                _Pragma("unroll 1")                                                     \
                for (int kk = 0; kk < D; kk += 8) {                                     \
                    _Pragma("unroll")                                                   \
                    for (int i = 0; i < 8; i++)                                         \
                        a1[i] = *reinterpret_cast<const float4*>((bX) + (r0 + i) * D + kk + 4); \
                    _Pragma("unroll")                                                   \
                    for (int dk = 0; dk < 4; dk++)                                      \
                        w1[dk] = *reinterpret_cast<const ulonglong2*>((sW) + (kk + 4 + dk) * D + c0); \
                    _Pragma("unroll")                                                   \
                    for (int dk = 0; dk < 4; dk++) {                                    \
                        _Pragma("unroll")                                               \
                        for (int i = 0; i < 8; i++) {                                   \
                            unsigned long long a2 = dup2(reinterpret_cast<const float*>(&a0[i])[dk]); \
                            accu[i][0] = fma2(a2, w0[dk].x, accu[i][0]);                \
                            accu[i][1] = fma2(a2, w0[dk].y, accu[i][1]);                \
                        }                                                               \
                    }                                                                   \
                    if (kk + 8 < D) {                                                   \
                        _Pragma("unroll")                                               \
                        for (int i = 0; i < 8; i++)                                     \
                            a0[i] = *reinterpret_cast<const float4*>((bX) + (r0 + i) * D + kk + 8); \
                        _Pragma("unroll")                                               \
                        for (int dk = 0; dk < 4; dk++)                                  \
                            w0[dk] = *reinterpret_cast<const ulonglong2*>((sW) + (kk + 8 + dk) * D + c0); \
                    }                                                                   \
                    _Pragma("unroll")                                                   \
                    for (int dk = 0; dk < 4; dk++) {                                    \
                        _Pragma("unroll")                                               \
                        for (int i = 0; i < 8; i++) {                                   \
                            unsigned long long a2 = dup2(reinterpret_cast<const float*>(&a1[i])[dk]); \
                            accu[i][0] = fma2(a2, w1[dk].x, accu[i][0]);                \
                            accu[i][1] = fma2(a2, w1[dk].y, accu[i][1]);                \
                        }                                                               \
                    }                                                                   \
                }                                                                       \
            }

            GEMM_PASS(bXs, sWs)   // pass 1: self x Ws
            GEMM_PASS(bXn, sWn)   // pass 2: neigh x Wn
            #undef GEMM_PASS

            #pragma unroll
            for (int i = 0; i < 8; i++) {
                int row = t * TILE + r0 + i;
                float2 lo = unpack2(accu[i][0]);
                float2 hi = unpack2(accu[i][1]);
                *reinterpret_cast<float4*>(out + (size_t)row * D + c0) =
                    make_float4(lo.x, lo.y, hi.x, hi.y);
            }
        }
        __syncthreads();
        p ^= 1;
    }
}

// ---------------- launch ----------------
extern "C" void kernel_launch(void* const* d_in, const int* in_sizes, int n_in,
                              void* d_out, int out_size) {
    const float* h      = (const float*)d_in[0];
    const void*  src    = d_in[1];
    const void*  dst    = d_in[2];
    const float* Wself  = (const float*)d_in[3];
    const float* Wneigh = (const float*)d_in[4];
    float*       out    = (float*)d_out;

    static bool attr_set = false;
    if (!attr_set) {
        cudaFuncSetAttribute(fused_kernel,
                             cudaFuncAttributeMaxDynamicSharedMemorySize,
                             196608);
        attr_set = true;
    }

    zero_sniff_kernel<<<NB_B, 256>>>(src);
    count_kernel<<<2048, 256>>>(dst);
    build_kernel<<<NB_B, 256>>>(src, dst);
    fused_kernel<<<152, 384, 196608>>>(h, Wself, Wneigh, out);
}